// round 3
// baseline (speedup 1.0000x reference)
#include <cuda_runtime.h>

// Fixed shapes: B=128, L=512, D=256, T=64, G=8
#define B_ 128
#define L_ 512
#define D_ 256
#define T_ 64
#define G_ 8
#define D4_ (D_/4)              // 64
#define NPOOL (B_*T_*D_)        // 2,097,152
#define NFULL (B_*L_*D_)        // 16,777,216
#define NFULL4 (NFULL/4)        // 4,194,304 float4 elements per modality

// Scratch (__device__ globals; allocation-free rule)
__device__ float g_hw[NPOOL];     // 8 MB : 0.5*(aco_p + vis_p)
__device__ float g_cpre[NPOOL];   // 8 MB : cw0*aco_p + cw1*vis_p
__device__ float g_scale[NPOOL];  // 8 MB : (h_att + w_att + c_att)/3

__device__ __forceinline__ float sigmoidf_(float x) {
    return 1.0f / (1.0f + __expf(-x));
}

__device__ __forceinline__ float4 ldcs4(const float4* p) {
    float4 r;
    asm volatile("ld.global.cs.v4.f32 {%0,%1,%2,%3}, [%4];"
                 : "=f"(r.x), "=f"(r.y), "=f"(r.z), "=f"(r.w) : "l"(p));
    return r;
}
__device__ __forceinline__ void stcs4(float4* p, float4 v) {
    asm volatile("st.global.cs.v4.f32 [%0], {%1,%2,%3,%4};"
                 :: "l"(p), "f"(v.x), "f"(v.y), "f"(v.z), "f"(v.w));
}

// ---------------------------------------------------------------------------
// Kernel 1: temporal pooling + derived-tensor fusion.
// Each thread produces one float4 of hw and cpre. Reads 128 MB once (evict-
// first: data is not reused until apply, far beyond L2 residency).
// ---------------------------------------------------------------------------
__global__ void __launch_bounds__(256) pool_kernel(const float* __restrict__ aco,
                                                   const float* __restrict__ vis,
                                                   const float* __restrict__ conv_w) {
    int idx = blockIdx.x * blockDim.x + threadIdx.x;     // over B*T*D/4
    int d4 = idx & (D4_ - 1);
    int t  = (idx >> 6) & (T_ - 1);
    int b  = idx >> 12;

    size_t base = (size_t)b * L_ * D4_ + (size_t)t * G_ * D4_ + d4;
    const float4* a4 = reinterpret_cast<const float4*>(aco) + base;
    const float4* v4 = reinterpret_cast<const float4*>(vis) + base;

    float4 sa = make_float4(0.f, 0.f, 0.f, 0.f);
    float4 sv = make_float4(0.f, 0.f, 0.f, 0.f);
#pragma unroll
    for (int g = 0; g < G_; g++) {
        float4 x = ldcs4(a4 + g * D4_);
        float4 y = ldcs4(v4 + g * D4_);
        sa.x += x.x; sa.y += x.y; sa.z += x.z; sa.w += x.w;
        sv.x += y.x; sv.y += y.y; sv.z += y.z; sv.w += y.w;
    }
    const float inv = 1.0f / (float)G_;   // mean over G
    sa.x *= inv; sa.y *= inv; sa.z *= inv; sa.w *= inv;
    sv.x *= inv; sv.y *= inv; sv.z *= inv; sv.w *= inv;

    const float cw0 = __ldg(conv_w + 0);
    const float cw1 = __ldg(conv_w + 1);

    float4 hw, cp;
    hw.x = 0.5f * (sa.x + sv.x);  cp.x = fmaf(cw0, sa.x, cw1 * sv.x);
    hw.y = 0.5f * (sa.y + sv.y);  cp.y = fmaf(cw0, sa.y, cw1 * sv.y);
    hw.z = 0.5f * (sa.z + sv.z);  cp.z = fmaf(cw0, sa.z, cw1 * sv.z);
    hw.w = 0.5f * (sa.w + sv.w);  cp.w = fmaf(cw0, sa.w, cw1 * sv.w);

    reinterpret_cast<float4*>(g_hw)[idx]   = hw;
    reinterpret_cast<float4*>(g_cpre)[idx] = cp;
}

// ---------------------------------------------------------------------------
// Kernel 2: per-batch attention + fused scale-tensor write.
// One block per batch, 256 threads. No block syncs inside reduction loops.
// ---------------------------------------------------------------------------
__global__ void __launch_bounds__(256) att_kernel(const float* __restrict__ Wh,
                                                  const float* __restrict__ bh,
                                                  const float* __restrict__ Ww,
                                                  const float* __restrict__ bw,
                                                  const float* __restrict__ conv_b) {
    int b    = blockIdx.x;
    int tid  = threadIdx.x;          // 0..255 (== d index)
    int lane = tid & 31;
    int wrp  = tid >> 5;             // 0..7

    __shared__ float s_hwm_t[T_];    // hw row means  (over D)
    __shared__ float s_hwm_d[D_];    // hw col means  (over T)
    __shared__ float s_hatt[T_];
    __shared__ float s_watt[D_];

    const float* hwp = g_hw + (size_t)b * T_ * D_;

    // --- column means (over T): thread tid owns column d = tid. Coalesced. ---
    {
        float cs = 0.f;
#pragma unroll 8
        for (int t = 0; t < T_; t++) cs += hwp[t * D_ + tid];
        s_hwm_d[tid] = cs * (1.0f / (float)T_);
    }

    // --- row means (over D): warp w owns rows t = w*8 .. w*8+7. -------------
#pragma unroll
    for (int r = 0; r < 8; r++) {
        int t = wrp * 8 + r;
        const float* row = hwp + t * D_;
        float s = 0.f;
#pragma unroll
        for (int k = 0; k < 8; k++) s += row[lane + 32 * k];
#pragma unroll
        for (int o = 16; o > 0; o >>= 1) s += __shfl_down_sync(0xffffffffu, s, o);
        if (lane == 0) s_hwm_t[t] = s * (1.0f / (float)D_);
    }
    __syncthreads();

    // --- h_att[i] = sigmoid(sum_j hwm_t[j]*Wh[i,j] + bh[i])   (threads 0..63)
    if (tid < T_) {
        float acc = __ldg(bh + tid);
        const float* wr = Wh + tid * T_;
#pragma unroll 8
        for (int j = 0; j < T_; j++) acc = fmaf(s_hwm_t[j], __ldg(wr + j), acc);
        s_hatt[tid] = sigmoidf_(acc);
    }
    // --- w_att[i] = sigmoid(sum_j hwm_d[j]*Ww[i,j] + bw[i])   (all 256) -----
    {
        float acc = __ldg(bw + tid);
        const float* wr = Ww + tid * D_;
#pragma unroll 8
        for (int j = 0; j < D_; j++) acc = fmaf(s_hwm_d[j], __ldg(wr + j), acc);
        s_watt[tid] = sigmoidf_(acc);
    }
    __syncthreads();

    // --- fused scale: S = (h_att[t] + w_att[d] + sigmoid(cpre + cb)) / 3 ----
    const float cb = __ldg(conv_b + 0);
    const float4* c4 = reinterpret_cast<const float4*>(g_cpre + (size_t)b * T_ * D_);
    float4* s4 = reinterpret_cast<float4*>(g_scale + (size_t)b * T_ * D_);

    const float third = 1.0f / 3.0f;
#pragma unroll 4
    for (int i = tid; i < T_ * D4_; i += 256) {
        int t  = i >> 6;
        int d4 = (i & 63) << 2;
        float4 c = c4[i];
        float h = s_hatt[t];
        float4 s;
        s.x = (h + s_watt[d4 + 0] + sigmoidf_(c.x + cb)) * third;
        s.y = (h + s_watt[d4 + 1] + sigmoidf_(c.y + cb)) * third;
        s.z = (h + s_watt[d4 + 2] + sigmoidf_(c.z + cb)) * third;
        s.w = (h + s_watt[d4 + 3] + sigmoidf_(c.w + cb)) * third;
        s4[i] = s;
    }
}

// ---------------------------------------------------------------------------
// Kernel 3: apply. ILP=2: each thread handles two float4 per modality.
// Streaming loads (.cs) for inputs, streaming stores (.cs) for outputs, so
// g_scale (8 MB) + isbag stay L2-resident.  Block tile = 512 float4.
// ---------------------------------------------------------------------------
__global__ void __launch_bounds__(256) apply_kernel(const float* __restrict__ aco,
                                                    const float* __restrict__ vis,
                                                    const int* __restrict__ isbag,
                                                    float* __restrict__ out) {
    int i0 = blockIdx.x * 512 + threadIdx.x;   // first float4 index
    int i1 = i0 + 256;                         // second float4 index

    const float4* a4 = reinterpret_cast<const float4*>(aco);
    const float4* v4 = reinterpret_cast<const float4*>(vis);
    const float4* s4 = reinterpret_cast<const float4*>(g_scale);
    float4* o4 = reinterpret_cast<float4*>(out);

    // Batched front loads -> MLP 4
    float4 a0 = ldcs4(a4 + i0);
    float4 a1 = ldcs4(a4 + i1);
    float4 v0 = ldcs4(v4 + i0);
    float4 v1 = ldcs4(v4 + i1);

#pragma unroll
    for (int k = 0; k < 2; k++) {
        int idx = (k == 0) ? i0 : i1;
        float4 a = (k == 0) ? a0 : a1;
        float4 v = (k == 0) ? v0 : v1;

        int d4 = idx & (D4_ - 1);
        int l  = (idx >> 6) & (L_ - 1);
        int b  = idx >> 15;            // L_*D4_ = 32768 float4 per batch
        int t  = l >> 3;               // t = l / G

        float4 s = s4[((b * T_ + t) << 6) + d4];
        bool m = (__ldg(isbag + b * L_ + l) == 1);
        float sx = m ? s.x : 1.0f;
        float sy = m ? s.y : 1.0f;
        float sz = m ? s.z : 1.0f;
        float sw = m ? s.w : 1.0f;

        stcs4(o4 + idx,          make_float4(a.x * sx, a.y * sy, a.z * sz, a.w * sw));
        stcs4(o4 + idx + NFULL4, make_float4(v.x * sx, v.y * sy, v.z * sz, v.w * sw));
    }
}

// ---------------------------------------------------------------------------
extern "C" void kernel_launch(void* const* d_in, const int* in_sizes, int n_in,
                              void* d_out, int out_size) {
    const float* aco    = (const float*)d_in[0];
    const float* vis    = (const float*)d_in[1];
    const int*   isbag  = (const int*)  d_in[2];
    const float* Wh     = (const float*)d_in[3];
    const float* bh     = (const float*)d_in[4];
    const float* Ww     = (const float*)d_in[5];
    const float* bw     = (const float*)d_in[6];
    const float* conv_w = (const float*)d_in[7];
    const float* conv_b = (const float*)d_in[8];
    float* out = (float*)d_out;

    (void)in_sizes; (void)n_in; (void)out_size;

    pool_kernel<<<NPOOL / 4 / 256, 256>>>(aco, vis, conv_w);
    att_kernel<<<B_, 256>>>(Wh, bh, Ww, bw, conv_b);
    apply_kernel<<<NFULL4 / 512, 256>>>(aco, vis, isbag, out);
}

// round 7
// speedup vs baseline: 1.1154x; 1.1154x over previous
#include <cuda_runtime.h>

// Fixed shapes: B=128, L=512, D=256, T=64, G=8
#define B_ 128
#define L_ 512
#define D_ 256
#define T_ 64
#define G_ 8
#define D4_ (D_/4)              // 64
#define NPOOL (B_*T_*D_)        // 2,097,152
#define NFULL (B_*L_*D_)        // 16,777,216
#define NFULL4 (NFULL/4)        // 4,194,304 float4 per modality
#define PARTS_ 16               // pool blocks per batch (each covers 4 t-rows)

// Scratch (__device__ globals; allocation-free rule)
__device__ float g_c3[NPOOL];                 // 8 MB : sigmoid(conv)/3
__device__ float g_rowsum[B_ * T_];           // 32 KB: sum_d hw[b,t,d]
__device__ float g_colpart[B_ * PARTS_ * D_]; // 2 MB : partial sum_t hw (4 t's/part)
__device__ float g_h3[B_ * T_];               // 32 KB: sigmoid(.@Wh^T+bh)/3
__device__ float g_w3[B_ * D_];               // 128 KB: sigmoid(.@Ww^T+bw)/3

__device__ __forceinline__ float sigmoidf_(float x) {
    return 1.0f / (1.0f + __expf(-x));
}

__device__ __forceinline__ float4 ldcs4(const float4* p) {
    float4 r;
    asm volatile("ld.global.cs.v4.f32 {%0,%1,%2,%3}, [%4];"
                 : "=f"(r.x), "=f"(r.y), "=f"(r.z), "=f"(r.w) : "l"(p));
    return r;
}
__device__ __forceinline__ void stcs4(float4* p, float4 v) {
    asm volatile("st.global.cs.v4.f32 [%0], {%1,%2,%3,%4};"
                 :: "l"(p), "f"(v.x), "f"(v.y), "f"(v.z), "f"(v.w));
}

// ---------------------------------------------------------------------------
// Kernel 1: pooling + c3 + in-block hw reductions. Block = (b, 4 t-rows, D).
// Writes c3 (8 MB), final per-(b,t) row sums, per-block column partials.
// hw is never materialized to gmem.
// ---------------------------------------------------------------------------
__global__ void __launch_bounds__(256) pool_kernel(const float* __restrict__ aco,
                                                   const float* __restrict__ vis,
                                                   const float* __restrict__ conv_w,
                                                   const float* __restrict__ conv_b) {
    int tid = threadIdx.x;
    int idx = blockIdx.x * 256 + tid;      // over B*T*D/4
    int d4 = idx & (D4_ - 1);
    int t  = (idx >> 6) & (T_ - 1);
    int b  = idx >> 12;
    int lane = tid & 31;
    int wrp  = tid >> 5;                   // 0..7 (warps 2r, 2r+1 own local row r)

    __shared__ float4 s_col[256];          // hw staging for column partials
    __shared__ float  s_warp[8];           // row-sum warp partials

    size_t base = (size_t)b * L_ * D4_ + (size_t)t * G_ * D4_ + d4;
    const float4* a4 = reinterpret_cast<const float4*>(aco) + base;
    const float4* v4 = reinterpret_cast<const float4*>(vis) + base;

    float4 sa = make_float4(0.f, 0.f, 0.f, 0.f);
    float4 sv = make_float4(0.f, 0.f, 0.f, 0.f);
#pragma unroll
    for (int g = 0; g < G_; g++) {
        float4 x = ldcs4(a4 + g * D4_);
        float4 y = ldcs4(v4 + g * D4_);
        sa.x += x.x; sa.y += x.y; sa.z += x.z; sa.w += x.w;
        sv.x += y.x; sv.y += y.y; sv.z += y.z; sv.w += y.w;
    }
    const float inv = 1.0f / (float)G_;
    sa.x *= inv; sa.y *= inv; sa.z *= inv; sa.w *= inv;
    sv.x *= inv; sv.y *= inv; sv.z *= inv; sv.w *= inv;

    // hw = 0.5*(aco_p + vis_p)
    float4 hw;
    hw.x = 0.5f * (sa.x + sv.x);
    hw.y = 0.5f * (sa.y + sv.y);
    hw.z = 0.5f * (sa.z + sv.z);
    hw.w = 0.5f * (sa.w + sv.w);

    // c3 = sigmoid(cw0*aco_p + cw1*vis_p + cb) / 3
    const float cw0 = __ldg(conv_w + 0);
    const float cw1 = __ldg(conv_w + 1);
    const float cb  = __ldg(conv_b + 0);
    const float third = 1.0f / 3.0f;
    float4 c3;
    c3.x = sigmoidf_(fmaf(cw0, sa.x, fmaf(cw1, sv.x, cb))) * third;
    c3.y = sigmoidf_(fmaf(cw0, sa.y, fmaf(cw1, sv.y, cb))) * third;
    c3.z = sigmoidf_(fmaf(cw0, sa.z, fmaf(cw1, sv.z, cb))) * third;
    c3.w = sigmoidf_(fmaf(cw0, sa.w, fmaf(cw1, sv.w, cb))) * third;
    reinterpret_cast<float4*>(g_c3)[idx] = c3;

    // ---- row sums (over D): warp-level shuffle tree ------------------------
    float rs = (hw.x + hw.y) + (hw.z + hw.w);
#pragma unroll
    for (int o = 16; o > 0; o >>= 1) rs += __shfl_down_sync(0xffffffffu, rs, o);
    if (lane == 0) s_warp[wrp] = rs;

    // ---- stage hw for column partials --------------------------------------
    s_col[tid] = hw;
    __syncthreads();

    if (tid < 4) {
        // final row sum for local row tid -> t = part*4 + tid
        g_rowsum[b * T_ + ((blockIdx.x & (PARTS_ - 1)) * 4 + tid)] =
            s_warp[2 * tid] + s_warp[2 * tid + 1];
    }
    if (tid < 64) {
        float4 c0 = s_col[tid];
        float4 c1 = s_col[64 + tid];
        float4 c2 = s_col[128 + tid];
        float4 c3v = s_col[192 + tid];
        float4 cp;
        cp.x = (c0.x + c1.x) + (c2.x + c3v.x);
        cp.y = (c0.y + c1.y) + (c2.y + c3v.y);
        cp.z = (c0.z + c1.z) + (c2.z + c3v.z);
        cp.w = (c0.w + c1.w) + (c2.w + c3v.w);
        reinterpret_cast<float4*>(g_colpart)[blockIdx.x * 64 + tid] = cp;
    }
}

// ---------------------------------------------------------------------------
// Kernel 2: finish means + two small matvecs. One block per batch.
// Reads ~17 KB/block (L2-hot) + broadcast weights. Writes 1.25 KB.
// ---------------------------------------------------------------------------
__global__ void __launch_bounds__(256) reduce_kernel(const float* __restrict__ Wh,
                                                     const float* __restrict__ bh,
                                                     const float* __restrict__ Ww,
                                                     const float* __restrict__ bw) {
    int b   = blockIdx.x;
    int tid = threadIdx.x;               // 0..255 (== d index)

    __shared__ float s_hwm_t[T_];
    __shared__ float s_hwm_d[D_];

    if (tid < T_)
        s_hwm_t[tid] = g_rowsum[b * T_ + tid] * (1.0f / (float)D_);

    {
        const float* cp = g_colpart + b * PARTS_ * D_ + tid;
        float cs = 0.f;
#pragma unroll
        for (int p = 0; p < PARTS_; p++) cs += cp[p * D_];
        s_hwm_d[tid] = cs * (1.0f / (float)T_);
    }
    __syncthreads();

    const float third = 1.0f / 3.0f;

    // h3[i] = sigmoid(hwm_t @ Wh[i,:] + bh[i]) / 3   (threads 0..63)
    if (tid < T_) {
        float acc = __ldg(bh + tid);
        const float* wr = Wh + tid * T_;
#pragma unroll 8
        for (int j = 0; j < T_; j++) acc = fmaf(s_hwm_t[j], __ldg(wr + j), acc);
        g_h3[b * T_ + tid] = sigmoidf_(acc) * third;
    }
    // w3[i] = sigmoid(hwm_d @ Ww[i,:] + bw[i]) / 3   (all 256 threads)
    {
        float acc = __ldg(bw + tid);
        const float* wr = Ww + tid * D_;
#pragma unroll 8
        for (int j = 0; j < D_; j++) acc = fmaf(s_hwm_d[j], __ldg(wr + j), acc);
        g_w3[b * D_ + tid] = sigmoidf_(acc) * third;
    }
}

// ---------------------------------------------------------------------------
// Kernel 3: apply. ILP=4, scale composed inline: s = h3[t] + w3[d] + c3[t,d].
// Streaming (.cs) on the 256 MB bulk; h3/w3/c3/mask stay cache-resident.
// ---------------------------------------------------------------------------
__global__ void __launch_bounds__(256) apply_kernel(const float* __restrict__ aco,
                                                    const float* __restrict__ vis,
                                                    const int* __restrict__ isbag,
                                                    float* __restrict__ out) {
    int base = blockIdx.x * 1024 + threadIdx.x;   // block tile = 1024 float4

    const float4* a4 = reinterpret_cast<const float4*>(aco);
    const float4* v4 = reinterpret_cast<const float4*>(vis);
    const float4* c4 = reinterpret_cast<const float4*>(g_c3);
    const float4* w4 = reinterpret_cast<const float4*>(g_w3);
    float4* o4 = reinterpret_cast<float4*>(out);

    float4 a[4], v[4];
#pragma unroll
    for (int k = 0; k < 4; k++) a[k] = ldcs4(a4 + base + k * 256);
#pragma unroll
    for (int k = 0; k < 4; k++) v[k] = ldcs4(v4 + base + k * 256);

#pragma unroll
    for (int k = 0; k < 4; k++) {
        int idx = base + k * 256;
        int d4 = idx & (D4_ - 1);
        int l  = (idx >> 6) & (L_ - 1);
        int b  = idx >> 15;            // L_*D4_ = 32768 float4 per batch
        int t  = l >> 3;               // t = l / G

        float4 c = __ldg(c4 + ((b * T_ + t) << 6) + d4);
        float4 w = __ldg(w4 + b * D4_ + d4);
        float  h = __ldg(g_h3 + b * T_ + t);
        bool   m = (__ldg(isbag + b * L_ + l) == 1);

        float sx = m ? (h + w.x + c.x) : 1.0f;
        float sy = m ? (h + w.y + c.y) : 1.0f;
        float sz = m ? (h + w.z + c.z) : 1.0f;
        float sw = m ? (h + w.w + c.w) : 1.0f;

        stcs4(o4 + idx,          make_float4(a[k].x * sx, a[k].y * sy, a[k].z * sz, a[k].w * sw));
        stcs4(o4 + idx + NFULL4, make_float4(v[k].x * sx, v[k].y * sy, v[k].z * sz, v[k].w * sw));
    }
}

// ---------------------------------------------------------------------------
extern "C" void kernel_launch(void* const* d_in, const int* in_sizes, int n_in,
                              void* d_out, int out_size) {
    const float* aco    = (const float*)d_in[0];
    const float* vis    = (const float*)d_in[1];
    const int*   isbag  = (const int*)  d_in[2];
    const float* Wh     = (const float*)d_in[3];
    const float* bh     = (const float*)d_in[4];
    const float* Ww     = (const float*)d_in[5];
    const float* bw     = (const float*)d_in[6];
    const float* conv_w = (const float*)d_in[7];
    const float* conv_b = (const float*)d_in[8];
    float* out = (float*)d_out;

    (void)in_sizes; (void)n_in; (void)out_size;

    pool_kernel<<<NPOOL / 4 / 256, 256>>>(aco, vis, conv_w, conv_b);
    reduce_kernel<<<B_, 256>>>(Wh, bh, Ww, bw);
    apply_kernel<<<NFULL4 / 1024, 256>>>(aco, vis, isbag, out);
}